// round 1
// baseline (speedup 1.0000x reference)
#include <cuda_runtime.h>
#include <math.h>

#define BB 4
#define CC 1024
#define DD 1024
#define HH 16
#define DHH 64
#define ROWS (BB*CC)          // 4096
#define ELEMS (BB*CC*DD)      // 4194304
#define ATTN_ELEMS (BB*HH*CC*CC)  // 67108864

// Scratch (allocation-free rule: __device__ globals)
__device__ float g_kn[ELEMS];
__device__ float g_vn[ELEMS];
__device__ float g_qp[ELEMS];
__device__ float g_kp[ELEMS];
__device__ float g_vp[ELEMS];
__device__ float g_ctx[ELEMS];
__device__ float g_proj[ELEMS];
__device__ float g_attn_scratch[ATTN_ELEMS];  // fallback if attn not in d_out

// ---------------------------------------------------------------------------
// LayerNorm: one block per row (D=1024), 256 threads x float4
// ---------------------------------------------------------------------------
__global__ __launch_bounds__(256) void ln_kernel(
    const float* __restrict__ x, const float* __restrict__ gam,
    const float* __restrict__ bet, float* __restrict__ y)
{
    int row = blockIdx.x;
    int tid = threadIdx.x;
    const float4 v = ((const float4*)(x + (size_t)row * DD))[tid];
    float s  = v.x + v.y + v.z + v.w;
    float ss = v.x*v.x + v.y*v.y + v.z*v.z + v.w*v.w;
    #pragma unroll
    for (int o = 16; o > 0; o >>= 1) {
        s  += __shfl_xor_sync(0xFFFFFFFFu, s, o);
        ss += __shfl_xor_sync(0xFFFFFFFFu, ss, o);
    }
    __shared__ float sh_s[8], sh_ss[8];
    __shared__ float sh_m, sh_r;
    int w = tid >> 5, l = tid & 31;
    if (l == 0) { sh_s[w] = s; sh_ss[w] = ss; }
    __syncthreads();
    if (tid == 0) {
        float S = 0.f, SS = 0.f;
        #pragma unroll
        for (int i = 0; i < 8; i++) { S += sh_s[i]; SS += sh_ss[i]; }
        float m = S * (1.0f / DD);
        float var = SS * (1.0f / DD) - m * m;
        sh_m = m;
        sh_r = rsqrtf(var + 1e-5f);
    }
    __syncthreads();
    float m = sh_m, r = sh_r;
    const float4 g4 = ((const float4*)gam)[tid];
    const float4 b4 = ((const float4*)bet)[tid];
    float4 o;
    o.x = (v.x - m) * r * g4.x + b4.x;
    o.y = (v.y - m) * r * g4.y + b4.y;
    o.z = (v.z - m) * r * g4.z + b4.z;
    o.w = (v.w - m) * r * g4.w + b4.w;
    ((float4*)(y + (size_t)row * DD))[tid] = o;
}

// ---------------------------------------------------------------------------
// Tiled SGEMM + bias:  C[M,N] = A[M,K] @ B[K,N] + bias[N]
// BM=BN=64, BK=16, 256 threads, 4x4 per thread
// ---------------------------------------------------------------------------
#define BM 64
#define BN 64
#define BK 16

__global__ __launch_bounds__(256) void gemm_bias_kernel(
    const float* __restrict__ A, const float* __restrict__ Bm,
    const float* __restrict__ bias, float* __restrict__ Cm,
    int M, int N, int K)
{
    __shared__ float As[BK][BM + 4];
    __shared__ float Bs[BK][BN + 4];
    int tid = threadIdx.x;
    int tx = tid & 15, ty = tid >> 4;
    int m0 = blockIdx.y * BM, n0 = blockIdx.x * BN;
    float acc[4][4] = {};
    for (int kt = 0; kt < K; kt += BK) {
        #pragma unroll
        for (int i = 0; i < 4; i++) {
            int idx = tid + i * 256;
            int m = idx >> 4, kk = idx & 15;
            As[kk][m] = A[(size_t)(m0 + m) * K + kt + kk];
        }
        #pragma unroll
        for (int i = 0; i < 4; i++) {
            int idx = tid + i * 256;
            int kk = idx >> 6, n = idx & 63;
            Bs[kk][n] = Bm[(size_t)(kt + kk) * N + n0 + n];
        }
        __syncthreads();
        #pragma unroll
        for (int kk = 0; kk < BK; kk++) {
            float a[4], b[4];
            #pragma unroll
            for (int i = 0; i < 4; i++) a[i] = As[kk][ty * 4 + i];
            #pragma unroll
            for (int j = 0; j < 4; j++) b[j] = Bs[kk][tx * 4 + j];
            #pragma unroll
            for (int i = 0; i < 4; i++)
                #pragma unroll
                for (int j = 0; j < 4; j++)
                    acc[i][j] += a[i] * b[j];
        }
        __syncthreads();
    }
    #pragma unroll
    for (int i = 0; i < 4; i++) {
        int m = m0 + ty * 4 + i;
        #pragma unroll
        for (int j = 0; j < 4; j++) {
            int n = n0 + tx * 4 + j;
            Cm[(size_t)m * N + n] = acc[i][j] + bias[n];
        }
    }
}

// ---------------------------------------------------------------------------
// Scores: per (b,h): S[c,k] = sum_d qh[c,d]*kh[k,d]   (K=64)
// A,B are [C x 64] slices of row-stride D
// ---------------------------------------------------------------------------
__global__ __launch_bounds__(256) void scores_kernel(
    const float* __restrict__ qp, const float* __restrict__ kp,
    float* __restrict__ attn)
{
    int bh = blockIdx.z;
    int b = bh >> 4, h = bh & 15;
    const float* A  = qp + (size_t)b * CC * DD + h * DHH;
    const float* Bp = kp + (size_t)b * CC * DD + h * DHH;
    float* Cp = attn + (size_t)bh * CC * CC;

    __shared__ float As[BK][BM + 4];
    __shared__ float Bs[BK][BN + 4];
    int tid = threadIdx.x;
    int tx = tid & 15, ty = tid >> 4;
    int m0 = blockIdx.y * BM, n0 = blockIdx.x * BN;
    float acc[4][4] = {};
    for (int kt = 0; kt < DHH; kt += BK) {
        #pragma unroll
        for (int i = 0; i < 4; i++) {
            int idx = tid + i * 256;
            int m = idx >> 4, kk = idx & 15;
            As[kk][m] = A [(size_t)(m0 + m) * DD + kt + kk];
            Bs[kk][m] = Bp[(size_t)(n0 + m) * DD + kt + kk];
        }
        __syncthreads();
        #pragma unroll
        for (int kk = 0; kk < BK; kk++) {
            float a[4], bb[4];
            #pragma unroll
            for (int i = 0; i < 4; i++) a[i]  = As[kk][ty * 4 + i];
            #pragma unroll
            for (int j = 0; j < 4; j++) bb[j] = Bs[kk][tx * 4 + j];
            #pragma unroll
            for (int i = 0; i < 4; i++)
                #pragma unroll
                for (int j = 0; j < 4; j++)
                    acc[i][j] += a[i] * bb[j];
        }
        __syncthreads();
    }
    #pragma unroll
    for (int i = 0; i < 4; i++)
        #pragma unroll
        for (int j = 0; j < 4; j++)
            Cp[(size_t)(m0 + ty * 4 + i) * CC + n0 + tx * 4 + j] = acc[i][j];
}

// ---------------------------------------------------------------------------
// In-place GELU(exact)*scale then softmax over rows of length C
// ---------------------------------------------------------------------------
__global__ __launch_bounds__(256) void softmax_kernel(float* __restrict__ attn)
{
    size_t row = blockIdx.x;
    float* r = attn + row * (size_t)CC;
    int tid = threadIdx.x;
    float4 v = ((float4*)r)[tid];
    const float scale = 0.125f;             // Dh^-0.5
    const float inv_sqrt2 = 0.70710678118654752f;
    float t0 = 0.5f * v.x * (1.0f + erff(v.x * inv_sqrt2)) * scale;
    float t1 = 0.5f * v.y * (1.0f + erff(v.y * inv_sqrt2)) * scale;
    float t2 = 0.5f * v.z * (1.0f + erff(v.z * inv_sqrt2)) * scale;
    float t3 = 0.5f * v.w * (1.0f + erff(v.w * inv_sqrt2)) * scale;

    float mx = fmaxf(fmaxf(t0, t1), fmaxf(t2, t3));
    #pragma unroll
    for (int o = 16; o > 0; o >>= 1)
        mx = fmaxf(mx, __shfl_xor_sync(0xFFFFFFFFu, mx, o));
    __shared__ float shm[8];
    __shared__ float shv;
    int w = tid >> 5, l = tid & 31;
    if (l == 0) shm[w] = mx;
    __syncthreads();
    if (tid == 0) {
        float M = shm[0];
        #pragma unroll
        for (int i = 1; i < 8; i++) M = fmaxf(M, shm[i]);
        shv = M;
    }
    __syncthreads();
    float M = shv;
    float e0 = __expf(t0 - M), e1 = __expf(t1 - M);
    float e2 = __expf(t2 - M), e3 = __expf(t3 - M);
    float s = e0 + e1 + e2 + e3;
    #pragma unroll
    for (int o = 16; o > 0; o >>= 1)
        s += __shfl_xor_sync(0xFFFFFFFFu, s, o);
    if (l == 0) shm[w] = s;
    __syncthreads();
    if (tid == 0) {
        float S = 0.f;
        #pragma unroll
        for (int i = 0; i < 8; i++) S += shm[i];
        shv = 1.0f / S;
    }
    __syncthreads();
    float inv = shv;
    float4 o;
    o.x = e0 * inv; o.y = e1 * inv; o.z = e2 * inv; o.w = e3 * inv;
    ((float4*)r)[tid] = o;
}

// ---------------------------------------------------------------------------
// ctx: per (b,h): ctx[c, h*64+d] = sum_k attn[c,k] * vp[k, h*64+d]
// M=C tiled by 64, N=64 (full head), K=C
// ---------------------------------------------------------------------------
__global__ __launch_bounds__(256) void ctx_kernel(
    const float* __restrict__ attn, const float* __restrict__ vp,
    float* __restrict__ ctx)
{
    int bh = blockIdx.z;
    int b = bh >> 4, h = bh & 15;
    const float* A  = attn + (size_t)bh * CC * CC;           // lda = C
    const float* Bp = vp  + (size_t)b * CC * DD + h * DHH;   // ldb = D
    float*       Cp = ctx + (size_t)b * CC * DD + h * DHH;   // ldc = D

    __shared__ float As[BK][BM + 4];
    __shared__ float Bs[BK][BN + 4];
    int tid = threadIdx.x;
    int tx = tid & 15, ty = tid >> 4;
    int m0 = blockIdx.y * BM;
    float acc[4][4] = {};
    for (int kt = 0; kt < CC; kt += BK) {
        #pragma unroll
        for (int i = 0; i < 4; i++) {
            int idx = tid + i * 256;
            int m = idx >> 4, kk = idx & 15;
            As[kk][m] = A[(size_t)(m0 + m) * CC + kt + kk];
        }
        #pragma unroll
        for (int i = 0; i < 4; i++) {
            int idx = tid + i * 256;
            int kk = idx >> 6, n = idx & 63;
            Bs[kk][n] = Bp[(size_t)(kt + kk) * DD + n];
        }
        __syncthreads();
        #pragma unroll
        for (int kk = 0; kk < BK; kk++) {
            float a[4], bb[4];
            #pragma unroll
            for (int i = 0; i < 4; i++) a[i]  = As[kk][ty * 4 + i];
            #pragma unroll
            for (int j = 0; j < 4; j++) bb[j] = Bs[kk][tx * 4 + j];
            #pragma unroll
            for (int i = 0; i < 4; i++)
                #pragma unroll
                for (int j = 0; j < 4; j++)
                    acc[i][j] += a[i] * bb[j];
        }
        __syncthreads();
    }
    #pragma unroll
    for (int i = 0; i < 4; i++)
        #pragma unroll
        for (int j = 0; j < 4; j++)
            Cp[(size_t)(m0 + ty * 4 + i) * DD + tx * 4 + j] = acc[i][j];
}

// ---------------------------------------------------------------------------
// L2 normalize rows: out = x / max(||x||, 1e-12)
// ---------------------------------------------------------------------------
__global__ __launch_bounds__(256) void l2norm_kernel(
    const float* __restrict__ x, float* __restrict__ y)
{
    int row = blockIdx.x;
    int tid = threadIdx.x;
    const float4 v = ((const float4*)(x + (size_t)row * DD))[tid];
    float ss = v.x*v.x + v.y*v.y + v.z*v.z + v.w*v.w;
    #pragma unroll
    for (int o = 16; o > 0; o >>= 1)
        ss += __shfl_xor_sync(0xFFFFFFFFu, ss, o);
    __shared__ float sh[8];
    __shared__ float shinv;
    int w = tid >> 5, l = tid & 31;
    if (l == 0) sh[w] = ss;
    __syncthreads();
    if (tid == 0) {
        float S = 0.f;
        #pragma unroll
        for (int i = 0; i < 8; i++) S += sh[i];
        shinv = 1.0f / fmaxf(sqrtf(S), 1e-12f);
    }
    __syncthreads();
    float inv = shinv;
    float4 o;
    o.x = v.x * inv; o.y = v.y * inv; o.z = v.z * inv; o.w = v.w * inv;
    ((float4*)(y + (size_t)row * DD))[tid] = o;
}

// ---------------------------------------------------------------------------
extern "C" void kernel_launch(void* const* d_in, const int* in_sizes, int n_in,
                              void* d_out, int out_size)
{
    const float* q      = (const float*)d_in[0];
    const float* k      = (const float*)d_in[1];
    const float* v      = (const float*)d_in[2];
    const float* ln_k_g = (const float*)d_in[3];
    const float* ln_k_b = (const float*)d_in[4];
    const float* ln_v_g = (const float*)d_in[5];
    const float* ln_v_b = (const float*)d_in[6];
    const float* Wq     = (const float*)d_in[7];
    const float* bq     = (const float*)d_in[8];
    const float* Wk     = (const float*)d_in[9];
    const float* bk     = (const float*)d_in[10];
    const float* Wv     = (const float*)d_in[11];
    const float* bv     = (const float*)d_in[12];
    const float* Wo     = (const float*)d_in[13];
    const float* bo     = (const float*)d_in[14];

    float* out = (float*)d_out;

    float *kn, *vn, *qp, *kp, *vp, *ctx, *proj, *attn_scr;
    cudaGetSymbolAddress((void**)&kn,   g_kn);
    cudaGetSymbolAddress((void**)&vn,   g_vn);
    cudaGetSymbolAddress((void**)&qp,   g_qp);
    cudaGetSymbolAddress((void**)&kp,   g_kp);
    cudaGetSymbolAddress((void**)&vp,   g_vp);
    cudaGetSymbolAddress((void**)&ctx,  g_ctx);
    cudaGetSymbolAddress((void**)&proj, g_proj);
    cudaGetSymbolAddress((void**)&attn_scr, g_attn_scratch);

    // Output layout: reference returns (out, attn). If d_out is big enough to
    // hold both concatenated, write attn after out; otherwise keep it in scratch.
    float* attn = (out_size >= (int)(ELEMS + ATTN_ELEMS)) ? (out + (size_t)ELEMS)
                                                          : attn_scr;

    // 1) LayerNorm k, v
    ln_kernel<<<ROWS, 256>>>(k, ln_k_g, ln_k_b, kn);
    ln_kernel<<<ROWS, 256>>>(v, ln_v_g, ln_v_b, vn);

    // 2) Projections
    dim3 gg(DD / BN, ROWS / BM);   // (16, 64)
    gemm_bias_kernel<<<gg, 256>>>(q,  Wq, bq, qp, ROWS, DD, DD);
    gemm_bias_kernel<<<gg, 256>>>(kn, Wk, bk, kp, ROWS, DD, DD);
    gemm_bias_kernel<<<gg, 256>>>(vn, Wv, bv, vp, ROWS, DD, DD);

    // 3) Scores per head -> attn region
    scores_kernel<<<dim3(CC / BN, CC / BM, BB * HH), 256>>>(qp, kp, attn);

    // 4) GELU * scale + softmax (in place)
    softmax_kernel<<<BB * HH * CC, 256>>>(attn);

    // 5) attn @ V per head
    ctx_kernel<<<dim3(1, CC / BM, BB * HH), 256>>>(attn, vp, ctx);

    // 6) Output projection + L2 normalize
    gemm_bias_kernel<<<gg, 256>>>(ctx, Wo, bo, proj, ROWS, DD, DD);
    l2norm_kernel<<<ROWS, 256>>>(proj, out);
}